// round 11
// baseline (speedup 1.0000x reference)
#include <cuda_runtime.h>
#include <cuda_fp16.h>
#include <cstdint>
#include <cstddef>

// ---------------------------------------------------------------------------
// Problem constants (fixed shapes)
// ---------------------------------------------------------------------------
static constexpr int MDIM = 8192;   // B*S
static constexpr int NDIM = 4096;   // D_OUT
static constexpr int KDIM = 4096;   // D_IN

static constexpr int MT = 128;      // M tile per CTA
static constexpr int NT = 128;      // N tile per CTA
static constexpr int KT = 64;       // K per pipeline stage
static constexpr int KB = KDIM / KT;          // 64 K-iterations per tile
static constexpr int NSTAGE = 3;

static constexpr int NTILES = (MDIM / MT) * (NDIM / NT);   // 2048
static constexpr int GRID   = 296;                          // 2 CTAs x 148 SMs

static constexpr int A_TILE_BYTES = MT * KT * 2;          // 16384
static constexpr int W_TILE_BYTES = NT * KT * 2;          // 16384
static constexpr int STAGE_BYTES  = A_TILE_BYTES + W_TILE_BYTES;  // 32768

static constexpr int SMEM_TOTAL = 1024 + NSTAGE * STAGE_BYTES;    // 99328/CTA

// Weight-conversion grid: 8 elements per thread, 256 threads per block.
static constexpr int WCONV_BLOCKS = NDIM * KDIM / 8 / 256;        // 8192

// ---------------------------------------------------------------------------
// Scratch (device globals). Pre-swizzled (SW128) SMEM-ready tile blocks:
//   A (x in fp16):   [mb(64)][kb(64)] blocks of 128 rows x 128B, 16KB each
//   W (q-8 in fp16): [nb(32)][kb(64)] blocks of 128 rows x 128B, 16KB each
// ---------------------------------------------------------------------------
__device__ __align__(1024) unsigned char g_Ah[(size_t)MDIM * KDIM * 2];
__device__ __align__(1024) unsigned char g_Wb[(size_t)NDIM * KDIM * 2];
__device__ float g_rowsum[MDIM];

// ---------------------------------------------------------------------------
// PTX helpers (base PTX only — nothing 'a'-gated)
// ---------------------------------------------------------------------------
__device__ __forceinline__ uint32_t smem_u32(const void* p) {
    uint32_t a;
    asm("{ .reg .u64 t; cvta.to.shared.u64 t, %1; cvt.u32.u64 %0, t; }"
        : "=r"(a) : "l"(p));
    return a;
}

__device__ __forceinline__ uint32_t swz(uint32_t b) {
    return b ^ ((b >> 3) & 0x70);
}

__device__ __forceinline__ void mbar_init(uint32_t mbar, uint32_t cnt) {
    asm volatile("mbarrier.init.shared.b64 [%0], %1;" :: "r"(mbar), "r"(cnt) : "memory");
}

__device__ __forceinline__ void mbar_arrive(uint32_t mbar) {
    asm volatile("mbarrier.arrive.shared.b64 _, [%0];" :: "r"(mbar) : "memory");
}

__device__ __forceinline__ void mbar_expect_tx(uint32_t mbar, uint32_t bytes) {
    asm volatile("mbarrier.arrive.expect_tx.shared.b64 _, [%0], %1;"
                 :: "r"(mbar), "r"(bytes) : "memory");
}

__device__ __forceinline__ void bar_wait(uint32_t mbar, uint32_t parity) {
    uint32_t done;
    asm volatile("{\n .reg .pred p;\n"
                 " mbarrier.try_wait.parity.acquire.cta.shared::cta.b64 p, [%1], %2;\n"
                 " selp.b32 %0, 1, 0, p;\n}"
                 : "=r"(done) : "r"(mbar), "r"(parity) : "memory");
    while (!done) {
        asm volatile("{\n .reg .pred p;\n"
                     " mbarrier.try_wait.parity.acquire.cta.shared::cta.b64 p, [%1], %2, 0x989680;\n"
                     " selp.b32 %0, 1, 0, p;\n}"
                     : "=r"(done) : "r"(mbar), "r"(parity) : "memory");
    }
}

__device__ __forceinline__ void bulk_g2s(uint32_t dst_smem, const void* src,
                                         uint32_t bytes, uint32_t mbar) {
    asm volatile(
        "cp.async.bulk.shared::cluster.global.mbarrier::complete_tx::bytes "
        "[%0], [%1], %2, [%3];"
        :: "r"(dst_smem), "l"(src), "r"(bytes), "r"(mbar) : "memory");
}

__device__ __forceinline__ void ldsm_x4(uint32_t& r0, uint32_t& r1,
                                        uint32_t& r2, uint32_t& r3, uint32_t addr) {
    asm volatile("ldmatrix.sync.aligned.m8n8.x4.shared.b16 {%0,%1,%2,%3}, [%4];"
                 : "=r"(r0), "=r"(r1), "=r"(r2), "=r"(r3) : "r"(addr));
}

__device__ __forceinline__ void mma_f16(float* c, uint32_t a0, uint32_t a1,
                                        uint32_t a2, uint32_t a3,
                                        uint32_t b0, uint32_t b1) {
    asm volatile("mma.sync.aligned.m16n8k16.row.col.f32.f16.f16.f32 "
                 "{%0,%1,%2,%3}, {%4,%5,%6,%7}, {%8,%9}, {%0,%1,%2,%3};"
                 : "+f"(c[0]), "+f"(c[1]), "+f"(c[2]), "+f"(c[3])
                 : "r"(a0), "r"(a1), "r"(a2), "r"(a3), "r"(b0), "r"(b1));
}

__device__ __forceinline__ uint32_t pack_h2f(float lo, float hi) {
    __half2 t = __floats2half2_rn(lo, hi);
    return *reinterpret_cast<uint32_t*>(&t);
}

// ---------------------------------------------------------------------------
// Fused prep: blocks [0, MDIM) convert x rows; blocks [MDIM, MDIM+WCONV_BLOCKS)
// convert weights (8 elems/thread).
// ---------------------------------------------------------------------------
__global__ void prep_kernel(const float* __restrict__ x, const int* __restrict__ q) {
    if (blockIdx.x < MDIM) {
        // ---- x fp32 -> fp16 plane (swizzled) + exact fp32 row sum ----
        const int m = blockIdx.x;
        const int t = threadIdx.x;    // 256 threads
        const float4* row = reinterpret_cast<const float4*>(x + (size_t)m * KDIM);
        const int mbb = m >> 7;
        const int r   = m & 127;
        const size_t abase = (size_t)mbb * ((size_t)KB * A_TILE_BYTES);

        float sum = 0.f;
        #pragma unroll
        for (int i = 0; i < 4; i++) {
            int g = t + i * 256;
            float4 v = row[g];
            sum += (v.x + v.y) + (v.z + v.w);

            int k0 = g << 2;
            int kb = k0 >> 6;
            int c0 = k0 & 63;
            size_t off = abase + (size_t)kb * A_TILE_BYTES
                       + swz((uint32_t)(r * 128 + c0 * 2));
            *reinterpret_cast<uint2*>(g_Ah + off) =
                make_uint2(pack_h2f(v.x, v.y), pack_h2f(v.z, v.w));
        }

        #pragma unroll
        for (int o = 16; o; o >>= 1) sum += __shfl_xor_sync(0xFFFFFFFFu, sum, o);
        __shared__ float ws[8];
        if ((t & 31) == 0) ws[t >> 5] = sum;
        __syncthreads();
        if (t == 0) {
            float s = 0.f;
            #pragma unroll
            for (int i = 0; i < 8; i++) s += ws[i];
            g_rowsum[m] = s;
        }
    } else {
        // ---- weight int32 (0..15) -> fp16 (q-8, exact), SW128 blocks ----
        int idx = (blockIdx.x - MDIM) * blockDim.x + threadIdx.x; // 8 elems/thr
        int n  = idx >> 9;            // 512 groups of 8 per row
        int k0 = (idx & 511) << 3;

        const int4* p = reinterpret_cast<const int4*>(q + (size_t)n * KDIM + k0);
        int4 a = p[0], b = p[1];
        uint32_t w0 = pack_h2f((float)(a.x - 8), (float)(a.y - 8));
        uint32_t w1 = pack_h2f((float)(a.z - 8), (float)(a.w - 8));
        uint32_t w2 = pack_h2f((float)(b.x - 8), (float)(b.y - 8));
        uint32_t w3 = pack_h2f((float)(b.z - 8), (float)(b.w - 8));

        int nb = n >> 7;              // 128-row N block
        int r  = n & 127;
        int kb = k0 >> 6;
        int c0 = k0 & 63;
        size_t off = ((size_t)(nb * KB + kb)) * W_TILE_BYTES
                   + swz((uint32_t)(r * 128 + c0 * 2));
        *reinterpret_cast<uint4*>(g_Wb + off) = make_uint4(w0, w1, w2, w3);
    }
}

// ---------------------------------------------------------------------------
// GEMM: persistent CTAs. 296 CTAs (2/SM), each loops tiles t = bid + 296*i.
// Pipeline (mbarrier parity) runs CONTINUOUSLY across tile boundaries: one
// fill for the whole kernel, epilogue overlapped with next tile's prefetch.
// 4 compute warps (32 rows x 128 cols each) + 1 producer warp = 160 threads.
// ---------------------------------------------------------------------------
__global__ void __launch_bounds__(160, 2)
qgemm_kernel(const float* __restrict__ scale_p,
             const float* __restrict__ zp_p,
             const float* __restrict__ bias,
             float* __restrict__ out)
{
    extern __shared__ __align__(1024) unsigned char smem[];
    const uint32_t sb = smem_u32(smem);
    const int tid = threadIdx.x;
    const int wid = tid >> 5;            // 0..4
    const int lid = tid & 31;
    const int bid = blockIdx.x;          // 0..295

    const uint32_t FULLB  = sb;          // 3 x 8B
    const uint32_t EMPTYB = sb + 32;     // 3 x 8B
    const uint32_t TILE0  = sb + 1024;

    if (tid == 0) {
        #pragma unroll
        for (int s = 0; s < NSTAGE; s++) {
            mbar_init(FULLB  + 8 * s, 1);
            mbar_init(EMPTYB + 8 * s, 4);   // one arrive per compute warp
        }
        asm volatile("fence.proxy.async.shared::cta;" ::: "memory");
    }
    __syncthreads();

    if (wid < 4 && lid == 0) {
        #pragma unroll
        for (int s = 0; s < NSTAGE; s++) mbar_arrive(EMPTYB + 8 * s);
    }

    if (wid == 4) {
        // ------------------------- producer (persistent) -------------------
        if (lid == 0) {
            int s = 0, ph = 0;
            for (int t = bid; t < NTILES; t += GRID) {
                const int mb = t >> 5;           // 0..63
                const int nb = t & 31;           // 0..31
                const unsigned char* aB = g_Ah + (size_t)mb * ((size_t)KB * A_TILE_BYTES);
                const unsigned char* wB = g_Wb + (size_t)nb * ((size_t)KB * W_TILE_BYTES);
                for (int kb = 0; kb < KB; kb++) {
                    bar_wait(EMPTYB + 8 * s, ph);
                    mbar_expect_tx(FULLB + 8 * s, STAGE_BYTES);
                    uint32_t d = TILE0 + s * STAGE_BYTES;
                    bulk_g2s(d,                aB + (size_t)kb * A_TILE_BYTES,
                             A_TILE_BYTES, FULLB + 8 * s);
                    bulk_g2s(d + A_TILE_BYTES, wB + (size_t)kb * W_TILE_BYTES,
                             W_TILE_BYTES, FULLB + 8 * s);
                    if (++s == NSTAGE) { s = 0; ph ^= 1; }
                }
            }
        }
        return;
    }

    // ------------------------- compute warps (persistent) -------------------
    const int wm = wid;              // M sub-tile (32 rows), warp covers all 128 N
    const int g  = lid >> 3;         // ldmatrix lane group 0..3
    const int lr = lid & 7;

    uint32_t aRow[2], aXor[2];
    #pragma unroll
    for (int mt = 0; mt < 2; mt++) {
        int r = wm * 32 + mt * 16 + (g & 1) * 8 + lr;
        aRow[mt] = (uint32_t)(r * 128);
        aXor[mt] = (uint32_t)((r & 7) << 4);
    }
    uint32_t bRow[8], bXor[8];
    #pragma unroll
    for (int bt = 0; bt < 8; bt++) {
        int r = bt * 16 + (g >> 1) * 8 + lr;     // N rows 0..127
        bRow[bt] = (uint32_t)(r * 128);
        bXor[bt] = (uint32_t)((r & 7) << 4);
    }
    const uint32_t aCol = (uint32_t)((g >> 1) * 16);
    const uint32_t bCol = (uint32_t)((g & 1) * 16);

    const float scl = *scale_p;
    const float zp  = *zp_p;
    const float czp = scl * (8.0f - zp);

    int s = 0, ph = 0;
    for (int t = bid; t < NTILES; t += GRID) {
        const int mb = t >> 5;
        const int nb = t & 31;

        float acc[2][16][4];
        #pragma unroll
        for (int mt = 0; mt < 2; mt++)
            #pragma unroll
            for (int nt = 0; nt < 16; nt++)
                #pragma unroll
                for (int j = 0; j < 4; j++) acc[mt][nt][j] = 0.f;

        for (int kb = 0; kb < KB; kb++) {
            bar_wait(FULLB + 8 * s, ph);
            const uint32_t dA = TILE0 + s * STAGE_BYTES;
            const uint32_t dW = dA + A_TILE_BYTES;

            #pragma unroll
            for (int ks = 0; ks < 4; ks++) {
                const uint32_t kOff = (uint32_t)(ks * 32);

                uint32_t bf[8][4];
                #pragma unroll
                for (int bt = 0; bt < 8; bt++) {
                    uint32_t off = bRow[bt] + ((kOff + bCol) ^ bXor[bt]);
                    ldsm_x4(bf[bt][0], bf[bt][1], bf[bt][2], bf[bt][3], dW + off);
                }
                uint32_t ah[2][4];
                #pragma unroll
                for (int mt = 0; mt < 2; mt++) {
                    uint32_t off = aRow[mt] + ((kOff + aCol) ^ aXor[mt]);
                    ldsm_x4(ah[mt][0], ah[mt][1], ah[mt][2], ah[mt][3], dA + off);
                }
                #pragma unroll
                for (int bt = 0; bt < 8; bt++) {
                    #pragma unroll
                    for (int mt = 0; mt < 2; mt++) {
                        mma_f16(acc[mt][2 * bt + 0], ah[mt][0], ah[mt][1], ah[mt][2], ah[mt][3],
                                bf[bt][0], bf[bt][1]);
                        mma_f16(acc[mt][2 * bt + 1], ah[mt][0], ah[mt][1], ah[mt][2], ah[mt][3],
                                bf[bt][2], bf[bt][3]);
                    }
                }
            }
            if (lid == 0) mbar_arrive(EMPTYB + 8 * s);
            if (++s == NSTAGE) { s = 0; ph ^= 1; }
        }

        // ---- epilogue for this tile (producer prefetches next tile) ----
        const int mRow0 = mb * MT + wm * 32;
        const int nCol0 = nb * NT;

        #pragma unroll
        for (int mt = 0; mt < 2; mt++) {
            const int r0 = mRow0 + mt * 16 + (lid >> 2);
            const int r1 = r0 + 8;
            const float base0 = czp * g_rowsum[r0];
            const float base1 = czp * g_rowsum[r1];
            float* o0 = out + (size_t)r0 * NDIM;
            float* o1 = out + (size_t)r1 * NDIM;
            #pragma unroll
            for (int nt = 0; nt < 16; nt++) {
                const int c = nCol0 + nt * 8 + 2 * (lid & 3);
                const float2 bv = *reinterpret_cast<const float2*>(bias + c);
                float2 v0, v1;
                v0.x = fmaf(scl, acc[mt][nt][0], base0 + bv.x);
                v0.y = fmaf(scl, acc[mt][nt][1], base0 + bv.y);
                v1.x = fmaf(scl, acc[mt][nt][2], base1 + bv.x);
                v1.y = fmaf(scl, acc[mt][nt][3], base1 + bv.y);
                *reinterpret_cast<float2*>(o0 + c) = v0;
                *reinterpret_cast<float2*>(o1 + c) = v1;
            }
        }
    }
}

// ---------------------------------------------------------------------------
// kernel_launch
// ---------------------------------------------------------------------------
extern "C" void kernel_launch(void* const* d_in, const int* in_sizes, int n_in,
                              void* d_out, int out_size)
{
    (void)in_sizes; (void)n_in; (void)out_size;
    const float* x     = (const float*)d_in[0];
    const int*   wq    = (const int*)  d_in[1];
    const float* scale = (const float*)d_in[2];
    const float* zp    = (const float*)d_in[3];
    const float* bias  = (const float*)d_in[4];
    float* out = (float*)d_out;

    // Fused prep: 8192 x-row blocks + 8192 weight blocks (8 elems/thread)
    prep_kernel<<<MDIM + WCONV_BLOCKS, 256>>>(x, wq);

    cudaFuncSetAttribute(qgemm_kernel,
                         cudaFuncAttributeMaxDynamicSharedMemorySize, SMEM_TOTAL);
    qgemm_kernel<<<GRID, 160, SMEM_TOTAL>>>(scale, zp, bias, out);
}

// round 12
// speedup vs baseline: 1.0542x; 1.0542x over previous
#include <cuda_runtime.h>
#include <cuda_fp16.h>
#include <cstdint>
#include <cstddef>

// ---------------------------------------------------------------------------
// Problem constants (fixed shapes)
// ---------------------------------------------------------------------------
static constexpr int MDIM = 8192;   // B*S
static constexpr int NDIM = 4096;   // D_OUT
static constexpr int KDIM = 4096;   // D_IN

static constexpr int MT = 128;      // M tile per CTA
static constexpr int NT = 128;      // N tile per CTA
static constexpr int KT = 64;       // K per pipeline stage
static constexpr int KB = KDIM / KT;          // 64 K-iterations per tile
static constexpr int NSTAGE = 3;

static constexpr int NTILES = (MDIM / MT) * (NDIM / NT);   // 2048
static constexpr int GRID   = 296;                          // 2 CTAs x 148 SMs

static constexpr int A_TILE_BYTES = MT * KT * 2;          // 16384
static constexpr int W_TILE_BYTES = NT * KT * 2;          // 16384
static constexpr int STAGE_BYTES  = A_TILE_BYTES + W_TILE_BYTES;  // 32768

static constexpr int SMEM_TOTAL = 1024 + NSTAGE * STAGE_BYTES;    // 99328/CTA

// Weight-conversion grid: 8 elements per thread, 256 threads per block.
static constexpr int WCONV_BLOCKS = NDIM * KDIM / 8 / 256;        // 8192

// ---------------------------------------------------------------------------
// Scratch (device globals). Pre-swizzled (SW128) SMEM-ready tile blocks:
//   A (x in fp16):   [mb(64)][kb(64)] blocks of 128 rows x 128B, 16KB each
//   W (q-8 in fp16): [nb(32)][kb(64)] blocks of 128 rows x 128B, 16KB each
// ---------------------------------------------------------------------------
__device__ __align__(1024) unsigned char g_Ah[(size_t)MDIM * KDIM * 2];
__device__ __align__(1024) unsigned char g_Wb[(size_t)NDIM * KDIM * 2];
__device__ float g_rowsum[MDIM];
__device__ int   g_ticket;          // dynamic tile scheduler (reset by prep)

// ---------------------------------------------------------------------------
// PTX helpers (base PTX only — nothing 'a'-gated)
// ---------------------------------------------------------------------------
__device__ __forceinline__ uint32_t smem_u32(const void* p) {
    uint32_t a;
    asm("{ .reg .u64 t; cvta.to.shared.u64 t, %1; cvt.u32.u64 %0, t; }"
        : "=r"(a) : "l"(p));
    return a;
}

__device__ __forceinline__ uint32_t swz(uint32_t b) {
    return b ^ ((b >> 3) & 0x70);
}

__device__ __forceinline__ void mbar_init(uint32_t mbar, uint32_t cnt) {
    asm volatile("mbarrier.init.shared.b64 [%0], %1;" :: "r"(mbar), "r"(cnt) : "memory");
}

__device__ __forceinline__ void mbar_arrive(uint32_t mbar) {
    asm volatile("mbarrier.arrive.shared.b64 _, [%0];" :: "r"(mbar) : "memory");
}

__device__ __forceinline__ void mbar_expect_tx(uint32_t mbar, uint32_t bytes) {
    asm volatile("mbarrier.arrive.expect_tx.shared.b64 _, [%0], %1;"
                 :: "r"(mbar), "r"(bytes) : "memory");
}

__device__ __forceinline__ void bar_wait(uint32_t mbar, uint32_t parity) {
    uint32_t done;
    asm volatile("{\n .reg .pred p;\n"
                 " mbarrier.try_wait.parity.acquire.cta.shared::cta.b64 p, [%1], %2;\n"
                 " selp.b32 %0, 1, 0, p;\n}"
                 : "=r"(done) : "r"(mbar), "r"(parity) : "memory");
    while (!done) {
        asm volatile("{\n .reg .pred p;\n"
                     " mbarrier.try_wait.parity.acquire.cta.shared::cta.b64 p, [%1], %2, 0x989680;\n"
                     " selp.b32 %0, 1, 0, p;\n}"
                     : "=r"(done) : "r"(mbar), "r"(parity) : "memory");
    }
}

__device__ __forceinline__ void bulk_g2s(uint32_t dst_smem, const void* src,
                                         uint32_t bytes, uint32_t mbar) {
    asm volatile(
        "cp.async.bulk.shared::cluster.global.mbarrier::complete_tx::bytes "
        "[%0], [%1], %2, [%3];"
        :: "r"(dst_smem), "l"(src), "r"(bytes), "r"(mbar) : "memory");
}

__device__ __forceinline__ void ldsm_x4(uint32_t& r0, uint32_t& r1,
                                        uint32_t& r2, uint32_t& r3, uint32_t addr) {
    asm volatile("ldmatrix.sync.aligned.m8n8.x4.shared.b16 {%0,%1,%2,%3}, [%4];"
                 : "=r"(r0), "=r"(r1), "=r"(r2), "=r"(r3) : "r"(addr));
}

__device__ __forceinline__ void mma_f16(float* c, uint32_t a0, uint32_t a1,
                                        uint32_t a2, uint32_t a3,
                                        uint32_t b0, uint32_t b1) {
    asm volatile("mma.sync.aligned.m16n8k16.row.col.f32.f16.f16.f32 "
                 "{%0,%1,%2,%3}, {%4,%5,%6,%7}, {%8,%9}, {%0,%1,%2,%3};"
                 : "+f"(c[0]), "+f"(c[1]), "+f"(c[2]), "+f"(c[3])
                 : "r"(a0), "r"(a1), "r"(a2), "r"(a3), "r"(b0), "r"(b1));
}

__device__ __forceinline__ uint32_t pack_h2f(float lo, float hi) {
    __half2 t = __floats2half2_rn(lo, hi);
    return *reinterpret_cast<uint32_t*>(&t);
}

// ---------------------------------------------------------------------------
// Fused prep: blocks [0, MDIM) convert x rows; blocks [MDIM, MDIM+WCONV_BLOCKS)
// convert weights (8 elems/thread). Also resets the GEMM tile ticket.
// ---------------------------------------------------------------------------
__global__ void prep_kernel(const float* __restrict__ x, const int* __restrict__ q) {
    if (blockIdx.x < MDIM) {
        // ---- x fp32 -> fp16 plane (swizzled) + exact fp32 row sum ----
        const int m = blockIdx.x;
        const int t = threadIdx.x;    // 256 threads
        if (m == 0 && t == 0) g_ticket = GRID;   // reset dynamic scheduler
        const float4* row = reinterpret_cast<const float4*>(x + (size_t)m * KDIM);
        const int mbb = m >> 7;
        const int r   = m & 127;
        const size_t abase = (size_t)mbb * ((size_t)KB * A_TILE_BYTES);

        float sum = 0.f;
        #pragma unroll
        for (int i = 0; i < 4; i++) {
            int g = t + i * 256;
            float4 v = row[g];
            sum += (v.x + v.y) + (v.z + v.w);

            int k0 = g << 2;
            int kb = k0 >> 6;
            int c0 = k0 & 63;
            size_t off = abase + (size_t)kb * A_TILE_BYTES
                       + swz((uint32_t)(r * 128 + c0 * 2));
            *reinterpret_cast<uint2*>(g_Ah + off) =
                make_uint2(pack_h2f(v.x, v.y), pack_h2f(v.z, v.w));
        }

        #pragma unroll
        for (int o = 16; o; o >>= 1) sum += __shfl_xor_sync(0xFFFFFFFFu, sum, o);
        __shared__ float ws[8];
        if ((t & 31) == 0) ws[t >> 5] = sum;
        __syncthreads();
        if (t == 0) {
            float s = 0.f;
            #pragma unroll
            for (int i = 0; i < 8; i++) s += ws[i];
            g_rowsum[m] = s;
        }
    } else {
        // ---- weight int32 (0..15) -> fp16 (q-8, exact), SW128 blocks ----
        int idx = (blockIdx.x - MDIM) * blockDim.x + threadIdx.x; // 8 elems/thr
        int n  = idx >> 9;            // 512 groups of 8 per row
        int k0 = (idx & 511) << 3;

        const int4* p = reinterpret_cast<const int4*>(q + (size_t)n * KDIM + k0);
        int4 a = p[0], b = p[1];
        uint32_t w0 = pack_h2f((float)(a.x - 8), (float)(a.y - 8));
        uint32_t w1 = pack_h2f((float)(a.z - 8), (float)(a.w - 8));
        uint32_t w2 = pack_h2f((float)(b.x - 8), (float)(b.y - 8));
        uint32_t w3 = pack_h2f((float)(b.z - 8), (float)(b.w - 8));

        int nb = n >> 7;              // 128-row N block
        int r  = n & 127;
        int kb = k0 >> 6;
        int c0 = k0 & 63;
        size_t off = ((size_t)(nb * KB + kb)) * W_TILE_BYTES
                   + swz((uint32_t)(r * 128 + c0 * 2));
        *reinterpret_cast<uint4*>(g_Wb + off) = make_uint4(w0, w1, w2, w3);
    }
}

// ---------------------------------------------------------------------------
// GEMM: persistent CTAs with DYNAMIC tile scheduling (atomic ticket).
// 296 CTAs (2/SM). Pipeline (stage ring) runs continuously across tiles;
// producer fetches tickets and publishes tile ids to consumers through a
// depth-2 smem id-ring with its own mbarrier pair (no __syncthreads, so the
// producer prefetches the next tile while consumers run the epilogue).
// ---------------------------------------------------------------------------
__global__ void __launch_bounds__(160, 2)
qgemm_kernel(const float* __restrict__ scale_p,
             const float* __restrict__ zp_p,
             const float* __restrict__ bias,
             float* __restrict__ out)
{
    extern __shared__ __align__(1024) unsigned char smem[];
    const uint32_t sb = smem_u32(smem);
    const int tid = threadIdx.x;
    const int wid = tid >> 5;            // 0..4
    const int lid = tid & 31;
    const int bid = blockIdx.x;          // 0..295

    const uint32_t FULLB  = sb;          // 3 x 8B  stage-full barriers
    const uint32_t EMPTYB = sb + 32;     // 3 x 8B  stage-empty barriers
    const uint32_t TFULL  = sb + 64;     // 2 x 8B  tile-id published
    const uint32_t TEMPTY = sb + 96;     // 2 x 8B  tile-id slot free
    const uint32_t TID    = sb + 128;    // 2 x 4B  tile ids
    const uint32_t TILE0  = sb + 1024;

    if (tid == 0) {
        #pragma unroll
        for (int s = 0; s < NSTAGE; s++) {
            mbar_init(FULLB  + 8 * s, 1);
            mbar_init(EMPTYB + 8 * s, 4);   // one arrive per compute warp
        }
        #pragma unroll
        for (int j = 0; j < 2; j++) {
            mbar_init(TFULL  + 8 * j, 1);
            mbar_init(TEMPTY + 8 * j, 4);
        }
        asm volatile("fence.proxy.async.shared::cta;" ::: "memory");
    }
    __syncthreads();

    if (wid < 4 && lid == 0) {
        #pragma unroll
        for (int s = 0; s < NSTAGE; s++) mbar_arrive(EMPTYB + 8 * s);
        #pragma unroll
        for (int j = 0; j < 2; j++)      mbar_arrive(TEMPTY + 8 * j);
    }

    if (wid == 4) {
        // ------------------- producer (persistent, dynamic) -----------------
        if (lid == 0) {
            int s = 0, ph = 0;       // stage ring cursor
            int tc = 0;              // tile-slot counter
            int t = bid;             // first tile statically assigned
            while (true) {
                // publish tile id t to consumers
                int j = tc & 1, jp = (tc >> 1) & 1;
                bar_wait(TEMPTY + 8 * j, jp);
                asm volatile("st.shared.b32 [%0], %1;"
                             :: "r"(TID + 4 * j), "r"(t) : "memory");
                mbar_arrive(TFULL + 8 * j);     // release-arrive orders the STS
                tc++;
                if (t >= NTILES) break;         // sentinel published; done

                const int mb = t >> 5;          // 0..63
                const int nb = t & 31;          // 0..31
                const unsigned char* aB = g_Ah + (size_t)mb * ((size_t)KB * A_TILE_BYTES);
                const unsigned char* wB = g_Wb + (size_t)nb * ((size_t)KB * W_TILE_BYTES);
                for (int kb = 0; kb < KB; kb++) {
                    bar_wait(EMPTYB + 8 * s, ph);
                    mbar_expect_tx(FULLB + 8 * s, STAGE_BYTES);
                    uint32_t d = TILE0 + s * STAGE_BYTES;
                    bulk_g2s(d,                aB + (size_t)kb * A_TILE_BYTES,
                             A_TILE_BYTES, FULLB + 8 * s);
                    bulk_g2s(d + A_TILE_BYTES, wB + (size_t)kb * W_TILE_BYTES,
                             W_TILE_BYTES, FULLB + 8 * s);
                    if (++s == NSTAGE) { s = 0; ph ^= 1; }
                }
                t = atomicAdd(&g_ticket, 1);    // fetch next tile dynamically
            }
        }
        return;
    }

    // ------------------- compute warps (persistent, dynamic) ----------------
    const int wm = wid;              // M sub-tile (32 rows), warp covers all 128 N
    const int g  = lid >> 3;         // ldmatrix lane group 0..3
    const int lr = lid & 7;

    uint32_t aRow[2], aXor[2];
    #pragma unroll
    for (int mt = 0; mt < 2; mt++) {
        int r = wm * 32 + mt * 16 + (g & 1) * 8 + lr;
        aRow[mt] = (uint32_t)(r * 128);
        aXor[mt] = (uint32_t)((r & 7) << 4);
    }
    uint32_t bRow[8], bXor[8];
    #pragma unroll
    for (int bt = 0; bt < 8; bt++) {
        int r = bt * 16 + (g >> 1) * 8 + lr;     // N rows 0..127
        bRow[bt] = (uint32_t)(r * 128);
        bXor[bt] = (uint32_t)((r & 7) << 4);
    }
    const uint32_t aCol = (uint32_t)((g >> 1) * 16);
    const uint32_t bCol = (uint32_t)((g & 1) * 16);

    const float scl = *scale_p;
    const float zp  = *zp_p;
    const float czp = scl * (8.0f - zp);

    int s = 0, ph = 0;               // stage ring cursor (mirrors producer)
    int tc = 0;                      // tile-slot counter
    while (true) {
        int j = tc & 1, jp = (tc >> 1) & 1;
        bar_wait(TFULL + 8 * j, jp); // acquire-wait orders the tile-id load
        int t;
        asm volatile("ld.shared.b32 %0, [%1];" : "=r"(t) : "r"(TID + 4 * j));
        if (lid == 0) mbar_arrive(TEMPTY + 8 * j);
        tc++;
        if (t >= NTILES) break;

        const int mb = t >> 5;
        const int nb = t & 31;

        float acc[2][16][4];
        #pragma unroll
        for (int mt = 0; mt < 2; mt++)
            #pragma unroll
            for (int nt = 0; nt < 16; nt++)
                #pragma unroll
                for (int jj = 0; jj < 4; jj++) acc[mt][nt][jj] = 0.f;

        for (int kb = 0; kb < KB; kb++) {
            bar_wait(FULLB + 8 * s, ph);
            const uint32_t dA = TILE0 + s * STAGE_BYTES;
            const uint32_t dW = dA + A_TILE_BYTES;

            #pragma unroll
            for (int ks = 0; ks < 4; ks++) {
                const uint32_t kOff = (uint32_t)(ks * 32);

                uint32_t bf[8][4];
                #pragma unroll
                for (int bt = 0; bt < 8; bt++) {
                    uint32_t off = bRow[bt] + ((kOff + bCol) ^ bXor[bt]);
                    ldsm_x4(bf[bt][0], bf[bt][1], bf[bt][2], bf[bt][3], dW + off);
                }
                uint32_t ah[2][4];
                #pragma unroll
                for (int mt = 0; mt < 2; mt++) {
                    uint32_t off = aRow[mt] + ((kOff + aCol) ^ aXor[mt]);
                    ldsm_x4(ah[mt][0], ah[mt][1], ah[mt][2], ah[mt][3], dA + off);
                }
                #pragma unroll
                for (int bt = 0; bt < 8; bt++) {
                    #pragma unroll
                    for (int mt = 0; mt < 2; mt++) {
                        mma_f16(acc[mt][2 * bt + 0], ah[mt][0], ah[mt][1], ah[mt][2], ah[mt][3],
                                bf[bt][0], bf[bt][1]);
                        mma_f16(acc[mt][2 * bt + 1], ah[mt][0], ah[mt][1], ah[mt][2], ah[mt][3],
                                bf[bt][2], bf[bt][3]);
                    }
                }
            }
            if (lid == 0) mbar_arrive(EMPTYB + 8 * s);
            if (++s == NSTAGE) { s = 0; ph ^= 1; }
        }

        // ---- epilogue (producer already prefetching the next tile) ----
        const int mRow0 = mb * MT + wm * 32;
        const int nCol0 = nb * NT;

        #pragma unroll
        for (int mt = 0; mt < 2; mt++) {
            const int r0 = mRow0 + mt * 16 + (lid >> 2);
            const int r1 = r0 + 8;
            const float base0 = czp * g_rowsum[r0];
            const float base1 = czp * g_rowsum[r1];
            float* o0 = out + (size_t)r0 * NDIM;
            float* o1 = out + (size_t)r1 * NDIM;
            #pragma unroll
            for (int nt = 0; nt < 16; nt++) {
                const int c = nCol0 + nt * 8 + 2 * (lid & 3);
                const float2 bv = *reinterpret_cast<const float2*>(bias + c);
                float2 v0, v1;
                v0.x = fmaf(scl, acc[mt][nt][0], base0 + bv.x);
                v0.y = fmaf(scl, acc[mt][nt][1], base0 + bv.y);
                v1.x = fmaf(scl, acc[mt][nt][2], base1 + bv.x);
                v1.y = fmaf(scl, acc[mt][nt][3], base1 + bv.y);
                *reinterpret_cast<float2*>(o0 + c) = v0;
                *reinterpret_cast<float2*>(o1 + c) = v1;
            }
        }
    }
}

// ---------------------------------------------------------------------------
// kernel_launch
// ---------------------------------------------------------------------------
extern "C" void kernel_launch(void* const* d_in, const int* in_sizes, int n_in,
                              void* d_out, int out_size)
{
    (void)in_sizes; (void)n_in; (void)out_size;
    const float* x     = (const float*)d_in[0];
    const int*   wq    = (const int*)  d_in[1];
    const float* scale = (const float*)d_in[2];
    const float* zp    = (const float*)d_in[3];
    const float* bias  = (const float*)d_in[4];
    float* out = (float*)d_out;

    // Fused prep: 8192 x-row blocks + 8192 weight blocks; resets g_ticket.
    prep_kernel<<<MDIM + WCONV_BLOCKS, 256>>>(x, wq);

    cudaFuncSetAttribute(qgemm_kernel,
                         cudaFuncAttributeMaxDynamicSharedMemorySize, SMEM_TOTAL);
    qgemm_kernel<<<GRID, 160, SMEM_TOTAL>>>(scale, zp, bias, out);
}

// round 13
// speedup vs baseline: 1.1717x; 1.1115x over previous
#include <cuda_runtime.h>
#include <cuda_fp16.h>
#include <cstdint>
#include <cstddef>

// ---------------------------------------------------------------------------
// Problem constants (fixed shapes)
// ---------------------------------------------------------------------------
static constexpr int MDIM = 8192;   // B*S
static constexpr int NDIM = 4096;   // D_OUT
static constexpr int KDIM = 4096;   // D_IN

static constexpr int MT = 128;      // M tile per CTA
static constexpr int NT = 128;      // N tile per CTA
static constexpr int KT = 64;       // K per pipeline stage
static constexpr int KB = KDIM / KT;          // 64 K-iterations per tile
static constexpr int NSTAGE = 3;

static constexpr int A_TILE_BYTES = MT * KT * 2;          // 16384
static constexpr int W_TILE_BYTES = NT * KT * 2;          // 16384
static constexpr int STAGE_BYTES  = A_TILE_BYTES + W_TILE_BYTES;  // 32768

static constexpr int SMEM_TOTAL = 1024 + NSTAGE * STAGE_BYTES;    // 99328/CTA

// Weight-conversion grid: 8 elements per thread, 256 threads per block.
static constexpr int WCONV_BLOCKS = NDIM * KDIM / 8 / 256;        // 8192

// ---------------------------------------------------------------------------
// Scratch (device globals). Pre-swizzled (SW128) SMEM-ready tile blocks:
//   A (x in fp16):   [mb(64)][kb(64)] blocks of 128 rows x 128B, 16KB each
//   W (q-8 in fp16): [nb(32)][kb(64)] blocks of 128 rows x 128B, 16KB each
// ---------------------------------------------------------------------------
__device__ __align__(1024) unsigned char g_Ah[(size_t)MDIM * KDIM * 2];
__device__ __align__(1024) unsigned char g_Wb[(size_t)NDIM * KDIM * 2];
__device__ float g_rowsum[MDIM];

// ---------------------------------------------------------------------------
// PTX helpers (base PTX only — nothing 'a'-gated)
// ---------------------------------------------------------------------------
__device__ __forceinline__ uint32_t smem_u32(const void* p) {
    uint32_t a;
    asm("{ .reg .u64 t; cvta.to.shared.u64 t, %1; cvt.u32.u64 %0, t; }"
        : "=r"(a) : "l"(p));
    return a;
}

__device__ __forceinline__ uint32_t swz(uint32_t b) {
    return b ^ ((b >> 3) & 0x70);
}

__device__ __forceinline__ void mbar_init(uint32_t mbar, uint32_t cnt) {
    asm volatile("mbarrier.init.shared.b64 [%0], %1;" :: "r"(mbar), "r"(cnt) : "memory");
}

__device__ __forceinline__ void mbar_arrive(uint32_t mbar) {
    asm volatile("mbarrier.arrive.shared.b64 _, [%0];" :: "r"(mbar) : "memory");
}

__device__ __forceinline__ void mbar_expect_tx(uint32_t mbar, uint32_t bytes) {
    asm volatile("mbarrier.arrive.expect_tx.shared.b64 _, [%0], %1;"
                 :: "r"(mbar), "r"(bytes) : "memory");
}

__device__ __forceinline__ void bar_wait(uint32_t mbar, uint32_t parity) {
    uint32_t done;
    asm volatile("{\n .reg .pred p;\n"
                 " mbarrier.try_wait.parity.acquire.cta.shared::cta.b64 p, [%1], %2;\n"
                 " selp.b32 %0, 1, 0, p;\n}"
                 : "=r"(done) : "r"(mbar), "r"(parity) : "memory");
    while (!done) {
        asm volatile("{\n .reg .pred p;\n"
                     " mbarrier.try_wait.parity.acquire.cta.shared::cta.b64 p, [%1], %2, 0x989680;\n"
                     " selp.b32 %0, 1, 0, p;\n}"
                     : "=r"(done) : "r"(mbar), "r"(parity) : "memory");
    }
}

// Non-blocking single-shot barrier poll (mbarrier.test_wait). Issued early so
// its ~149-cycle latency hides behind MMA issue; result consumed at the next
// stage boundary.
__device__ __forceinline__ uint32_t bar_test(uint32_t mbar, uint32_t parity) {
    uint32_t done;
    asm volatile("{\n .reg .pred p;\n"
                 " mbarrier.test_wait.parity.acquire.cta.shared::cta.b64 p, [%1], %2;\n"
                 " selp.b32 %0, 1, 0, p;\n}"
                 : "=r"(done) : "r"(mbar), "r"(parity) : "memory");
    return done;
}

__device__ __forceinline__ void bulk_g2s(uint32_t dst_smem, const void* src,
                                         uint32_t bytes, uint32_t mbar) {
    asm volatile(
        "cp.async.bulk.shared::cluster.global.mbarrier::complete_tx::bytes "
        "[%0], [%1], %2, [%3];"
        :: "r"(dst_smem), "l"(src), "r"(bytes), "r"(mbar) : "memory");
}

__device__ __forceinline__ void ldsm_x4(uint32_t& r0, uint32_t& r1,
                                        uint32_t& r2, uint32_t& r3, uint32_t addr) {
    asm volatile("ldmatrix.sync.aligned.m8n8.x4.shared.b16 {%0,%1,%2,%3}, [%4];"
                 : "=r"(r0), "=r"(r1), "=r"(r2), "=r"(r3) : "r"(addr));
}

__device__ __forceinline__ void mma_f16(float* c, uint32_t a0, uint32_t a1,
                                        uint32_t a2, uint32_t a3,
                                        uint32_t b0, uint32_t b1) {
    asm volatile("mma.sync.aligned.m16n8k16.row.col.f32.f16.f16.f32 "
                 "{%0,%1,%2,%3}, {%4,%5,%6,%7}, {%8,%9}, {%0,%1,%2,%3};"
                 : "+f"(c[0]), "+f"(c[1]), "+f"(c[2]), "+f"(c[3])
                 : "r"(a0), "r"(a1), "r"(a2), "r"(a3), "r"(b0), "r"(b1));
}

__device__ __forceinline__ uint32_t pack_h2f(float lo, float hi) {
    __half2 t = __floats2half2_rn(lo, hi);
    return *reinterpret_cast<uint32_t*>(&t);
}

// ---------------------------------------------------------------------------
// Fused prep: blocks [0, MDIM) convert x rows; blocks [MDIM, MDIM+WCONV_BLOCKS)
// convert weights (8 elems/thread).
// ---------------------------------------------------------------------------
__global__ void prep_kernel(const float* __restrict__ x, const int* __restrict__ q) {
    if (blockIdx.x < MDIM) {
        // ---- x fp32 -> fp16 plane (swizzled) + exact fp32 row sum ----
        const int m = blockIdx.x;
        const int t = threadIdx.x;    // 256 threads
        const float4* row = reinterpret_cast<const float4*>(x + (size_t)m * KDIM);
        const int mbb = m >> 7;
        const int r   = m & 127;
        const size_t abase = (size_t)mbb * ((size_t)KB * A_TILE_BYTES);

        float sum = 0.f;
        #pragma unroll
        for (int i = 0; i < 4; i++) {
            int g = t + i * 256;
            float4 v = row[g];
            sum += (v.x + v.y) + (v.z + v.w);

            int k0 = g << 2;
            int kb = k0 >> 6;
            int c0 = k0 & 63;
            size_t off = abase + (size_t)kb * A_TILE_BYTES
                       + swz((uint32_t)(r * 128 + c0 * 2));
            *reinterpret_cast<uint2*>(g_Ah + off) =
                make_uint2(pack_h2f(v.x, v.y), pack_h2f(v.z, v.w));
        }

        #pragma unroll
        for (int o = 16; o; o >>= 1) sum += __shfl_xor_sync(0xFFFFFFFFu, sum, o);
        __shared__ float ws[8];
        if ((t & 31) == 0) ws[t >> 5] = sum;
        __syncthreads();
        if (t == 0) {
            float s = 0.f;
            #pragma unroll
            for (int i = 0; i < 8; i++) s += ws[i];
            g_rowsum[m] = s;
        }
    } else {
        // ---- weight int32 (0..15) -> fp16 (q-8, exact), SW128 blocks ----
        int idx = (blockIdx.x - MDIM) * blockDim.x + threadIdx.x; // 8 elems/thr
        int n  = idx >> 9;            // 512 groups of 8 per row
        int k0 = (idx & 511) << 3;

        const int4* p = reinterpret_cast<const int4*>(q + (size_t)n * KDIM + k0);
        int4 a = p[0], b = p[1];
        uint32_t w0 = pack_h2f((float)(a.x - 8), (float)(a.y - 8));
        uint32_t w1 = pack_h2f((float)(a.z - 8), (float)(a.w - 8));
        uint32_t w2 = pack_h2f((float)(b.x - 8), (float)(b.y - 8));
        uint32_t w3 = pack_h2f((float)(b.z - 8), (float)(b.w - 8));

        int nb = n >> 7;              // 128-row N block
        int r  = n & 127;
        int kb = k0 >> 6;
        int c0 = k0 & 63;
        size_t off = ((size_t)(nb * KB + kb)) * W_TILE_BYTES
                   + swz((uint32_t)(r * 128 + c0 * 2));
        *reinterpret_cast<uint4*>(g_Wb + off) = make_uint4(w0, w1, w2, w3);
    }
}

// ---------------------------------------------------------------------------
// GEMM: 128x128 CTA tile, 2 CTAs/SM, 4 compute warps + 1 producer.
// Stage-boundary waits software-pipelined: a non-blocking test_wait for the
// NEXT stage is issued between ks=2 and ks=3 of the current stage; when the
// pipeline is healthy the blocking wait is skipped entirely.
// ---------------------------------------------------------------------------
__global__ void __launch_bounds__(160, 2)
qgemm_kernel(const float* __restrict__ scale_p,
             const float* __restrict__ zp_p,
             const float* __restrict__ bias,
             float* __restrict__ out)
{
    extern __shared__ __align__(1024) unsigned char smem[];
    const uint32_t sb = smem_u32(smem);
    const int tid = threadIdx.x;
    const int wid = tid >> 5;            // 0..4
    const int lid = tid & 31;
    const int mb  = blockIdx.y;          // 0..63
    const int nb  = blockIdx.x;          // 0..31

    const uint32_t FULLB  = sb;          // 3 x 8B
    const uint32_t EMPTYB = sb + 32;     // 3 x 8B
    const uint32_t TILE0  = sb + 1024;

    if (tid == 0) {
        #pragma unroll
        for (int s = 0; s < NSTAGE; s++) {
            mbar_init(FULLB  + 8 * s, 1);
            mbar_init(EMPTYB + 8 * s, 4);   // one arrive per compute warp
        }
        asm volatile("fence.proxy.async.shared::cta;" ::: "memory");
    }
    __syncthreads();

    if (wid < 4 && lid == 0) {
        #pragma unroll
        for (int s = 0; s < NSTAGE; s++) mbar_arrive(EMPTYB + 8 * s);
    }

    if (wid == 4) {
        // ------------------------- producer -------------------------
        if (lid == 0) {
            const unsigned char* aB = g_Ah + (size_t)mb * ((size_t)KB * A_TILE_BYTES);
            const unsigned char* wB = g_Wb + (size_t)nb * ((size_t)KB * W_TILE_BYTES);
            int s = 0, ph = 0;
            for (int kb = 0; kb < KB; kb++) {
                bar_wait(EMPTYB + 8 * s, ph);
                mbar_expect_tx(FULLB + 8 * s, STAGE_BYTES);
                uint32_t d = TILE0 + s * STAGE_BYTES;
                bulk_g2s(d,                aB + (size_t)kb * A_TILE_BYTES,
                         A_TILE_BYTES, FULLB + 8 * s);
                bulk_g2s(d + A_TILE_BYTES, wB + (size_t)kb * W_TILE_BYTES,
                         W_TILE_BYTES, FULLB + 8 * s);
                if (++s == NSTAGE) { s = 0; ph ^= 1; }
            }
        }
        return;
    }

    // ------------------------- compute warps -------------------------
    const int wm = wid;              // M sub-tile (32 rows), warp covers all 128 N
    const int g  = lid >> 3;         // ldmatrix lane group 0..3
    const int lr = lid & 7;

    uint32_t aRow[2], aXor[2];
    #pragma unroll
    for (int mt = 0; mt < 2; mt++) {
        int r = wm * 32 + mt * 16 + (g & 1) * 8 + lr;
        aRow[mt] = (uint32_t)(r * 128);
        aXor[mt] = (uint32_t)((r & 7) << 4);
    }
    uint32_t bRow[8], bXor[8];
    #pragma unroll
    for (int bt = 0; bt < 8; bt++) {
        int r = bt * 16 + (g >> 1) * 8 + lr;     // N rows 0..127
        bRow[bt] = (uint32_t)(r * 128);
        bXor[bt] = (uint32_t)((r & 7) << 4);
    }
    const uint32_t aCol = (uint32_t)((g >> 1) * 16);
    const uint32_t bCol = (uint32_t)((g & 1) * 16);

    float acc[2][16][4];
    #pragma unroll
    for (int mt = 0; mt < 2; mt++)
        #pragma unroll
        for (int nt = 0; nt < 16; nt++)
            #pragma unroll
            for (int j = 0; j < 4; j++) acc[mt][nt][j] = 0.f;

    int s = 0, ph = 0;
    uint32_t pre = 0;                // next-stage barrier already known-full?
    for (int kb = 0; kb < KB; kb++) {
        if (!pre) bar_wait(FULLB + 8 * s, ph);
        const uint32_t dA = TILE0 + s * STAGE_BYTES;
        const uint32_t dW = dA + A_TILE_BYTES;
        const int      sn  = (s + 1 == NSTAGE) ? 0 : s + 1;
        const uint32_t phn = (s + 1 == NSTAGE) ? (uint32_t)(ph ^ 1) : (uint32_t)ph;

        #pragma unroll
        for (int ks = 0; ks < 4; ks++) {
            const uint32_t kOff = (uint32_t)(ks * 32);

            // Early non-blocking poll of the NEXT stage's full barrier;
            // latency (~149 cyc) hides behind the remaining chunk's MMAs.
            if (ks == 3)
                pre = (kb + 1 < KB) ? bar_test(FULLB + 8 * sn, phn) : 0u;

            uint32_t bf[8][4];
            #pragma unroll
            for (int bt = 0; bt < 8; bt++) {
                uint32_t off = bRow[bt] + ((kOff + bCol) ^ bXor[bt]);
                ldsm_x4(bf[bt][0], bf[bt][1], bf[bt][2], bf[bt][3], dW + off);
            }
            uint32_t ah[2][4];
            #pragma unroll
            for (int mt = 0; mt < 2; mt++) {
                uint32_t off = aRow[mt] + ((kOff + aCol) ^ aXor[mt]);
                ldsm_x4(ah[mt][0], ah[mt][1], ah[mt][2], ah[mt][3], dA + off);
            }
            #pragma unroll
            for (int bt = 0; bt < 8; bt++) {
                #pragma unroll
                for (int mt = 0; mt < 2; mt++) {
                    mma_f16(acc[mt][2 * bt + 0], ah[mt][0], ah[mt][1], ah[mt][2], ah[mt][3],
                            bf[bt][0], bf[bt][1]);
                    mma_f16(acc[mt][2 * bt + 1], ah[mt][0], ah[mt][1], ah[mt][2], ah[mt][3],
                            bf[bt][2], bf[bt][3]);
                }
            }
        }
        if (lid == 0) mbar_arrive(EMPTYB + 8 * s);
        s = sn; ph = (int)phn;
    }

    // ------------------------- epilogue -------------------------
    const float scl = *scale_p;
    const float zp  = *zp_p;
    const float czp = scl * (8.0f - zp);
    const int mRow0 = mb * MT + wm * 32;
    const int nCol0 = nb * NT;

    #pragma unroll
    for (int mt = 0; mt < 2; mt++) {
        const int r0 = mRow0 + mt * 16 + (lid >> 2);
        const int r1 = r0 + 8;
        const float base0 = czp * g_rowsum[r0];
        const float base1 = czp * g_rowsum[r1];
        float* o0 = out + (size_t)r0 * NDIM;
        float* o1 = out + (size_t)r1 * NDIM;
        #pragma unroll
        for (int nt = 0; nt < 16; nt++) {
            const int c = nCol0 + nt * 8 + 2 * (lid & 3);
            const float2 bv = *reinterpret_cast<const float2*>(bias + c);
            float2 v0, v1;
            v0.x = fmaf(scl, acc[mt][nt][0], base0 + bv.x);
            v0.y = fmaf(scl, acc[mt][nt][1], base0 + bv.y);
            v1.x = fmaf(scl, acc[mt][nt][2], base1 + bv.x);
            v1.y = fmaf(scl, acc[mt][nt][3], base1 + bv.y);
            *reinterpret_cast<float2*>(o0 + c) = v0;
            *reinterpret_cast<float2*>(o1 + c) = v1;
        }
    }
}

// ---------------------------------------------------------------------------
// kernel_launch
// ---------------------------------------------------------------------------
extern "C" void kernel_launch(void* const* d_in, const int* in_sizes, int n_in,
                              void* d_out, int out_size)
{
    (void)in_sizes; (void)n_in; (void)out_size;
    const float* x     = (const float*)d_in[0];
    const int*   wq    = (const int*)  d_in[1];
    const float* scale = (const float*)d_in[2];
    const float* zp    = (const float*)d_in[3];
    const float* bias  = (const float*)d_in[4];
    float* out = (float*)d_out;

    // Fused prep: 8192 x-row blocks + 8192 weight blocks (8 elems/thread)
    prep_kernel<<<MDIM + WCONV_BLOCKS, 256>>>(x, wq);

    cudaFuncSetAttribute(qgemm_kernel,
                         cudaFuncAttributeMaxDynamicSharedMemorySize, SMEM_TOTAL);
    dim3 grid(NDIM / NT, MDIM / MT);   // (32, 64)
    qgemm_kernel<<<grid, 160, SMEM_TOTAL>>>(scale, zp, bias, out);
}

// round 14
// speedup vs baseline: 1.1725x; 1.0007x over previous
#include <cuda_runtime.h>
#include <cuda_fp16.h>
#include <cstdint>
#include <cstddef>

// ---------------------------------------------------------------------------
// Problem constants (fixed shapes)
// ---------------------------------------------------------------------------
static constexpr int MDIM = 8192;   // B*S
static constexpr int NDIM = 4096;   // D_OUT
static constexpr int KDIM = 4096;   // D_IN

static constexpr int MT = 128;      // M tile per CTA
static constexpr int NT = 128;      // N tile per CTA
static constexpr int KT = 64;       // K per pipeline stage
static constexpr int KB = KDIM / KT;          // 64 K-iterations per tile
static constexpr int NSTAGE = 3;

static constexpr int A_TILE_BYTES = MT * KT * 2;          // 16384
static constexpr int W_TILE_BYTES = NT * KT * 2;          // 16384
static constexpr int STAGE_BYTES  = A_TILE_BYTES + W_TILE_BYTES;  // 32768

static constexpr int SMEM_TOTAL = 1024 + NSTAGE * STAGE_BYTES;    // 99328/CTA

// Weight-conversion grid: 8 elements per thread, 256 threads per block.
static constexpr int WCONV_BLOCKS = NDIM * KDIM / 8 / 256;        // 8192

// ---------------------------------------------------------------------------
// Scratch (device globals). Pre-swizzled (SW128) SMEM-ready tile blocks:
//   A (x in fp16):   [mb(64)][kb(64)] blocks of 128 rows x 128B, 16KB each
//   W (q-8 in fp16): [nb(32)][kb(64)] blocks of 128 rows x 128B, 16KB each
// ---------------------------------------------------------------------------
__device__ __align__(1024) unsigned char g_Ah[(size_t)MDIM * KDIM * 2];
__device__ __align__(1024) unsigned char g_Wb[(size_t)NDIM * KDIM * 2];
__device__ float g_rowsum[MDIM];

// ---------------------------------------------------------------------------
// PTX helpers (base PTX only — nothing 'a'-gated)
// ---------------------------------------------------------------------------
__device__ __forceinline__ uint32_t smem_u32(const void* p) {
    uint32_t a;
    asm("{ .reg .u64 t; cvta.to.shared.u64 t, %1; cvt.u32.u64 %0, t; }"
        : "=r"(a) : "l"(p));
    return a;
}

__device__ __forceinline__ uint32_t swz(uint32_t b) {
    return b ^ ((b >> 3) & 0x70);
}

__device__ __forceinline__ void mbar_init(uint32_t mbar, uint32_t cnt) {
    asm volatile("mbarrier.init.shared.b64 [%0], %1;" :: "r"(mbar), "r"(cnt) : "memory");
}

__device__ __forceinline__ void mbar_arrive(uint32_t mbar) {
    asm volatile("mbarrier.arrive.shared.b64 _, [%0];" :: "r"(mbar) : "memory");
}

__device__ __forceinline__ void mbar_expect_tx(uint32_t mbar, uint32_t bytes) {
    asm volatile("mbarrier.arrive.expect_tx.shared.b64 _, [%0], %1;"
                 :: "r"(mbar), "r"(bytes) : "memory");
}

__device__ __forceinline__ void bar_wait(uint32_t mbar, uint32_t parity) {
    uint32_t done;
    asm volatile("{\n .reg .pred p;\n"
                 " mbarrier.try_wait.parity.acquire.cta.shared::cta.b64 p, [%1], %2;\n"
                 " selp.b32 %0, 1, 0, p;\n}"
                 : "=r"(done) : "r"(mbar), "r"(parity) : "memory");
    while (!done) {
        asm volatile("{\n .reg .pred p;\n"
                     " mbarrier.try_wait.parity.acquire.cta.shared::cta.b64 p, [%1], %2, 0x989680;\n"
                     " selp.b32 %0, 1, 0, p;\n}"
                     : "=r"(done) : "r"(mbar), "r"(parity) : "memory");
    }
}

// Non-blocking single-shot barrier poll (mbarrier.test_wait). Issued early so
// its latency hides behind MMA issue; result consumed at the next boundary.
__device__ __forceinline__ uint32_t bar_test(uint32_t mbar, uint32_t parity) {
    uint32_t done;
    asm volatile("{\n .reg .pred p;\n"
                 " mbarrier.test_wait.parity.acquire.cta.shared::cta.b64 p, [%1], %2;\n"
                 " selp.b32 %0, 1, 0, p;\n}"
                 : "=r"(done) : "r"(mbar), "r"(parity) : "memory");
    return done;
}

__device__ __forceinline__ void bulk_g2s(uint32_t dst_smem, const void* src,
                                         uint32_t bytes, uint32_t mbar) {
    asm volatile(
        "cp.async.bulk.shared::cluster.global.mbarrier::complete_tx::bytes "
        "[%0], [%1], %2, [%3];"
        :: "r"(dst_smem), "l"(src), "r"(bytes), "r"(mbar) : "memory");
}

__device__ __forceinline__ void ldsm_x4(uint32_t& r0, uint32_t& r1,
                                        uint32_t& r2, uint32_t& r3, uint32_t addr) {
    asm volatile("ldmatrix.sync.aligned.m8n8.x4.shared.b16 {%0,%1,%2,%3}, [%4];"
                 : "=r"(r0), "=r"(r1), "=r"(r2), "=r"(r3) : "r"(addr));
}

__device__ __forceinline__ void mma_f16(float* c, uint32_t a0, uint32_t a1,
                                        uint32_t a2, uint32_t a3,
                                        uint32_t b0, uint32_t b1) {
    asm volatile("mma.sync.aligned.m16n8k16.row.col.f32.f16.f16.f32 "
                 "{%0,%1,%2,%3}, {%4,%5,%6,%7}, {%8,%9}, {%0,%1,%2,%3};"
                 : "+f"(c[0]), "+f"(c[1]), "+f"(c[2]), "+f"(c[3])
                 : "r"(a0), "r"(a1), "r"(a2), "r"(a3), "r"(b0), "r"(b1));
}

__device__ __forceinline__ uint32_t pack_h2f(float lo, float hi) {
    __half2 t = __floats2half2_rn(lo, hi);
    return *reinterpret_cast<uint32_t*>(&t);
}

// ---------------------------------------------------------------------------
// Fused prep: blocks [0, MDIM) convert x rows; blocks [MDIM, MDIM+WCONV_BLOCKS)
// convert weights (8 elems/thread).
// ---------------------------------------------------------------------------
__global__ void prep_kernel(const float* __restrict__ x, const int* __restrict__ q) {
    if (blockIdx.x < MDIM) {
        // ---- x fp32 -> fp16 plane (swizzled) + exact fp32 row sum ----
        const int m = blockIdx.x;
        const int t = threadIdx.x;    // 256 threads
        const float4* row = reinterpret_cast<const float4*>(x + (size_t)m * KDIM);
        const int mbb = m >> 7;
        const int r   = m & 127;
        const size_t abase = (size_t)mbb * ((size_t)KB * A_TILE_BYTES);

        float sum = 0.f;
        #pragma unroll
        for (int i = 0; i < 4; i++) {
            int g = t + i * 256;
            float4 v = row[g];
            sum += (v.x + v.y) + (v.z + v.w);

            int k0 = g << 2;
            int kb = k0 >> 6;
            int c0 = k0 & 63;
            size_t off = abase + (size_t)kb * A_TILE_BYTES
                       + swz((uint32_t)(r * 128 + c0 * 2));
            *reinterpret_cast<uint2*>(g_Ah + off) =
                make_uint2(pack_h2f(v.x, v.y), pack_h2f(v.z, v.w));
        }

        #pragma unroll
        for (int o = 16; o; o >>= 1) sum += __shfl_xor_sync(0xFFFFFFFFu, sum, o);
        __shared__ float ws[8];
        if ((t & 31) == 0) ws[t >> 5] = sum;
        __syncthreads();
        if (t == 0) {
            float s = 0.f;
            #pragma unroll
            for (int i = 0; i < 8; i++) s += ws[i];
            g_rowsum[m] = s;
        }
    } else {
        // ---- weight int32 (0..15) -> fp16 (q-8, exact), SW128 blocks ----
        int idx = (blockIdx.x - MDIM) * blockDim.x + threadIdx.x; // 8 elems/thr
        int n  = idx >> 9;            // 512 groups of 8 per row
        int k0 = (idx & 511) << 3;

        const int4* p = reinterpret_cast<const int4*>(q + (size_t)n * KDIM + k0);
        int4 a = p[0], b = p[1];
        uint32_t w0 = pack_h2f((float)(a.x - 8), (float)(a.y - 8));
        uint32_t w1 = pack_h2f((float)(a.z - 8), (float)(a.w - 8));
        uint32_t w2 = pack_h2f((float)(b.x - 8), (float)(b.y - 8));
        uint32_t w3 = pack_h2f((float)(b.z - 8), (float)(b.w - 8));

        int nb = n >> 7;              // 128-row N block
        int r  = n & 127;
        int kb = k0 >> 6;
        int c0 = k0 & 63;
        size_t off = ((size_t)(nb * KB + kb)) * W_TILE_BYTES
                   + swz((uint32_t)(r * 128 + c0 * 2));
        *reinterpret_cast<uint4*>(g_Wb + off) = make_uint4(w0, w1, w2, w3);
    }
}

// ---------------------------------------------------------------------------
// GEMM: 128x128 CTA tile, 2 CTAs/SM, 4 compute warps + 1 producer.
// (1) test_wait prefetch of the next stage's FULL barrier (round 13),
// (2) EMPTY arrive moved to right after the LAST smem read (chunk-3 ldsm) —
//     mbarrier.arrive release semantics order the prior shared reads, so the
//     producer gets a ~500-cycle head start per stage on refills.
// ---------------------------------------------------------------------------
__global__ void __launch_bounds__(160, 2)
qgemm_kernel(const float* __restrict__ scale_p,
             const float* __restrict__ zp_p,
             const float* __restrict__ bias,
             float* __restrict__ out)
{
    extern __shared__ __align__(1024) unsigned char smem[];
    const uint32_t sb = smem_u32(smem);
    const int tid = threadIdx.x;
    const int wid = tid >> 5;            // 0..4
    const int lid = tid & 31;
    const int mb  = blockIdx.y;          // 0..63
    const int nb  = blockIdx.x;          // 0..31

    const uint32_t FULLB  = sb;          // 3 x 8B
    const uint32_t EMPTYB = sb + 32;     // 3 x 8B
    const uint32_t TILE0  = sb + 1024;

    if (tid == 0) {
        #pragma unroll
        for (int s = 0; s < NSTAGE; s++) {
            mbar_init(FULLB  + 8 * s, 1);
            mbar_init(EMPTYB + 8 * s, 4);   // one arrive per compute warp
        }
        asm volatile("fence.proxy.async.shared::cta;" ::: "memory");
    }
    __syncthreads();

    if (wid < 4 && lid == 0) {
        #pragma unroll
        for (int s = 0; s < NSTAGE; s++) mbar_arrive(EMPTYB + 8 * s);
    }

    if (wid == 4) {
        // ------------------------- producer -------------------------
        if (lid == 0) {
            const unsigned char* aB = g_Ah + (size_t)mb * ((size_t)KB * A_TILE_BYTES);
            const unsigned char* wB = g_Wb + (size_t)nb * ((size_t)KB * W_TILE_BYTES);
            int s = 0, ph = 0;
            for (int kb = 0; kb < KB; kb++) {
                bar_wait(EMPTYB + 8 * s, ph);
                mbar_expect_tx(FULLB + 8 * s, STAGE_BYTES);
                uint32_t d = TILE0 + s * STAGE_BYTES;
                bulk_g2s(d,                aB + (size_t)kb * A_TILE_BYTES,
                         A_TILE_BYTES, FULLB + 8 * s);
                bulk_g2s(d + A_TILE_BYTES, wB + (size_t)kb * W_TILE_BYTES,
                         W_TILE_BYTES, FULLB + 8 * s);
                if (++s == NSTAGE) { s = 0; ph ^= 1; }
            }
        }
        return;
    }

    // ------------------------- compute warps -------------------------
    const int wm = wid;              // M sub-tile (32 rows), warp covers all 128 N
    const int g  = lid >> 3;         // ldmatrix lane group 0..3
    const int lr = lid & 7;

    uint32_t aRow[2], aXor[2];
    #pragma unroll
    for (int mt = 0; mt < 2; mt++) {
        int r = wm * 32 + mt * 16 + (g & 1) * 8 + lr;
        aRow[mt] = (uint32_t)(r * 128);
        aXor[mt] = (uint32_t)((r & 7) << 4);
    }
    uint32_t bRow[8], bXor[8];
    #pragma unroll
    for (int bt = 0; bt < 8; bt++) {
        int r = bt * 16 + (g >> 1) * 8 + lr;     // N rows 0..127
        bRow[bt] = (uint32_t)(r * 128);
        bXor[bt] = (uint32_t)((r & 7) << 4);
    }
    const uint32_t aCol = (uint32_t)((g >> 1) * 16);
    const uint32_t bCol = (uint32_t)((g & 1) * 16);

    float acc[2][16][4];
    #pragma unroll
    for (int mt = 0; mt < 2; mt++)
        #pragma unroll
        for (int nt = 0; nt < 16; nt++)
            #pragma unroll
            for (int j = 0; j < 4; j++) acc[mt][nt][j] = 0.f;

    int s = 0, ph = 0;
    uint32_t pre = 0;                // next-stage barrier already known-full?
    for (int kb = 0; kb < KB; kb++) {
        if (!pre) bar_wait(FULLB + 8 * s, ph);
        const uint32_t dA = TILE0 + s * STAGE_BYTES;
        const uint32_t dW = dA + A_TILE_BYTES;
        const int      sn  = (s + 1 == NSTAGE) ? 0 : s + 1;
        const uint32_t phn = (s + 1 == NSTAGE) ? (uint32_t)(ph ^ 1) : (uint32_t)ph;

        #pragma unroll
        for (int ks = 0; ks < 4; ks++) {
            const uint32_t kOff = (uint32_t)(ks * 32);

            // Early non-blocking poll of the NEXT stage's full barrier.
            if (ks == 3)
                pre = (kb + 1 < KB) ? bar_test(FULLB + 8 * sn, phn) : 0u;

            uint32_t bf[8][4];
            #pragma unroll
            for (int bt = 0; bt < 8; bt++) {
                uint32_t off = bRow[bt] + ((kOff + bCol) ^ bXor[bt]);
                ldsm_x4(bf[bt][0], bf[bt][1], bf[bt][2], bf[bt][3], dW + off);
            }
            uint32_t ah[2][4];
            #pragma unroll
            for (int mt = 0; mt < 2; mt++) {
                uint32_t off = aRow[mt] + ((kOff + aCol) ^ aXor[mt]);
                ldsm_x4(ah[mt][0], ah[mt][1], ah[mt][2], ah[mt][3], dA + off);
            }

            // EARLY empty-arrive: chunk 3's ldsm were the LAST smem reads of
            // this stage; the release-arrive orders them, and the producer
            // gets a ~500-cycle head start while we run the MMA sweep below.
            if (ks == 3 && lid == 0) mbar_arrive(EMPTYB + 8 * s);

            #pragma unroll
            for (int bt = 0; bt < 8; bt++) {
                #pragma unroll
                for (int mt = 0; mt < 2; mt++) {
                    mma_f16(acc[mt][2 * bt + 0], ah[mt][0], ah[mt][1], ah[mt][2], ah[mt][3],
                            bf[bt][0], bf[bt][1]);
                    mma_f16(acc[mt][2 * bt + 1], ah[mt][0], ah[mt][1], ah[mt][2], ah[mt][3],
                            bf[bt][2], bf[bt][3]);
                }
            }
        }
        s = sn; ph = (int)phn;
    }

    // ------------------------- epilogue -------------------------
    const float scl = *scale_p;
    const float zp  = *zp_p;
    const float czp = scl * (8.0f - zp);
    const int mRow0 = mb * MT + wm * 32;
    const int nCol0 = nb * NT;

    #pragma unroll
    for (int mt = 0; mt < 2; mt++) {
        const int r0 = mRow0 + mt * 16 + (lid >> 2);
        const int r1 = r0 + 8;
        const float base0 = czp * g_rowsum[r0];
        const float base1 = czp * g_rowsum[r1];
        float* o0 = out + (size_t)r0 * NDIM;
        float* o1 = out + (size_t)r1 * NDIM;
        #pragma unroll
        for (int nt = 0; nt < 16; nt++) {
            const int c = nCol0 + nt * 8 + 2 * (lid & 3);
            const float2 bv = *reinterpret_cast<const float2*>(bias + c);
            float2 v0, v1;
            v0.x = fmaf(scl, acc[mt][nt][0], base0 + bv.x);
            v0.y = fmaf(scl, acc[mt][nt][1], base0 + bv.y);
            v1.x = fmaf(scl, acc[mt][nt][2], base1 + bv.x);
            v1.y = fmaf(scl, acc[mt][nt][3], base1 + bv.y);
            *reinterpret_cast<float2*>(o0 + c) = v0;
            *reinterpret_cast<float2*>(o1 + c) = v1;
        }
    }
}

// ---------------------------------------------------------------------------
// kernel_launch
// ---------------------------------------------------------------------------
extern "C" void kernel_launch(void* const* d_in, const int* in_sizes, int n_in,
                              void* d_out, int out_size)
{
    (void)in_sizes; (void)n_in; (void)out_size;
    const float* x     = (const float*)d_in[0];
    const int*   wq    = (const int*)  d_in[1];
    const float* scale = (const float*)d_in[2];
    const float* zp    = (const float*)d_in[3];
    const float* bias  = (const float*)d_in[4];
    float* out = (float*)d_out;

    // Fused prep: 8192 x-row blocks + 8192 weight blocks (8 elems/thread)
    prep_kernel<<<MDIM + WCONV_BLOCKS, 256>>>(x, wq);

    cudaFuncSetAttribute(qgemm_kernel,
                         cudaFuncAttributeMaxDynamicSharedMemorySize, SMEM_TOTAL);
    dim3 grid(NDIM / NT, MDIM / MT);   // (32, 64)
    qgemm_kernel<<<grid, 160, SMEM_TOTAL>>>(scale, zp, bias, out);
}